// round 6
// baseline (speedup 1.0000x reference)
#include <cuda_runtime.h>

// ---------------------------------------------------------------------------
// Static scratch (no allocations allowed). N_NODES = 50000 in the reference.
// CAP = max binned in-degree: in-degree is Poisson(16); P(deg >= 96) ~ 1e-45.
// Both fill & reduce clamp to CAP (worst case wrong value, never a crash).
//
// g_deg starts zeroed (.bss). fill increments it; reduce consumes the count
// and writes 0 back, restoring the invariant for the next graph replay.
// ---------------------------------------------------------------------------
#define MAXN 50048
#define CAP  96

__device__ int g_deg[MAXN];
__device__ int g_bin[MAXN * CAP];   // ~19.2 MB: src ids grouped by dst

// ---------------------------------------------------------------------------
// Kernel 1: bin edges by destination. 4 edges per thread via int4 loads.
// ---------------------------------------------------------------------------
__global__ void fill_kernel4(const int4* __restrict__ src4,
                             const int4* __restrict__ dst4,
                             int n4, int n_nodes) {
    int i = blockIdx.x * blockDim.x + threadIdx.x;
    if (i >= n4) return;
    int4 s = __ldg(src4 + i);
    int4 t = __ldg(dst4 + i);

    #pragma unroll
    for (int u = 0; u < 4; u++) {
        int ss = (u == 0) ? s.x : (u == 1) ? s.y : (u == 2) ? s.z : s.w;
        int tt = (u == 0) ? t.x : (u == 1) ? t.y : (u == 2) ? t.z : t.w;
        if ((unsigned)ss >= (unsigned)n_nodes || (unsigned)tt >= (unsigned)n_nodes)
            continue;
        int pos = atomicAdd(&g_deg[tt], 1);
        if (pos < CAP) g_bin[tt * CAP + pos] = ss;
    }
}

__global__ void fill_kernel_tail(const int* __restrict__ src,
                                 const int* __restrict__ dst,
                                 int e0, int n_edges, int n_nodes) {
    int e = e0 + blockIdx.x * blockDim.x + threadIdx.x;
    if (e >= n_edges) return;
    int s = __ldg(src + e);
    int t = __ldg(dst + e);
    if ((unsigned)s >= (unsigned)n_nodes || (unsigned)t >= (unsigned)n_nodes) return;
    int pos = atomicAdd(&g_deg[t], 1);
    if (pos < CAP) g_bin[t * CAP + pos] = s;
}

// ---------------------------------------------------------------------------
// Kernel 2: warp-per-node gather-reduce + mean, float4 path with explicit
// 8-deep load batching to force MLP (R4 version had regs=26 -> MLP~4 ->
// latency-bound at L2=32%). Lane c in [0,24) owns 16B chunk c of the 384B
// feature row. Fast path for k <= 32 (P(k>32) ~ 1e-4); generic path otherwise.
// Lane 0 consumes g_deg[node] and resets it for the next graph replay.
// ---------------------------------------------------------------------------
__global__ void __launch_bounds__(256, 4)
reduce_kernel(const float* __restrict__ feat,
              float* __restrict__ out,
              int n_nodes) {
    const int lane = threadIdx.x & 31;
    const int warp = threadIdx.x >> 5;
    const int node = blockIdx.x * (blockDim.x >> 5) + warp;
    if (node >= n_nodes) return;

    int k = 0;
    if (lane == 0) {
        k = g_deg[node];
        g_deg[node] = 0;               // restore invariant for next replay
    }
    k = __shfl_sync(0xffffffffu, k, 0);
    k = k < CAP ? k : CAP;

    const int base = node * CAP;
    const bool active = lane < 24;
    float4 acc = make_float4(0.f, 0.f, 0.f, 0.f);

    if (k <= 32) {
        // ---- fast path: all ids in one register per lane ----
        int id = 0;
        if (lane < k) id = __ldg(g_bin + base + lane);

        for (int j0 = 0; j0 < k; j0 += 8) {
            float4 v[8];
            #pragma unroll
            for (int u = 0; u < 8; u++) {
                int sid = __shfl_sync(0xffffffffu, id, (j0 + u) & 31);
                v[u] = make_float4(0.f, 0.f, 0.f, 0.f);
                if (active && (j0 + u < k)) {
                    const float4* fp = reinterpret_cast<const float4*>(
                        feat + (size_t)sid * 96);
                    v[u] = __ldg(fp + lane);
                }
            }
            #pragma unroll
            for (int u = 0; u < 8; u++) {
                acc.x += v[u].x; acc.y += v[u].y;
                acc.z += v[u].z; acc.w += v[u].w;
            }
        }
    } else {
        // ---- rare generic path (a handful of nodes per call) ----
        for (int j = 0; j < k; j++) {
            int sid = __shfl_sync(0xffffffffu,
                                  (lane == (j & 31)) ? __ldg(g_bin + base + j) : 0,
                                  j & 31);
            if (active) {
                const float4* fp = reinterpret_cast<const float4*>(
                    feat + (size_t)sid * 96);
                float4 v = __ldg(fp + lane);
                acc.x += v.x; acc.y += v.y; acc.z += v.z; acc.w += v.w;
            }
        }
    }

    if (active) {
        const float inv = 1.0f / fmaxf((float)k, 1.0f);
        acc.x *= inv; acc.y *= inv; acc.z *= inv; acc.w *= inv;
        float4* o = reinterpret_cast<float4*>(out + (size_t)node * 96);
        o[lane] = acc;
    }
}

// ---------------------------------------------------------------------------
// Launch. Inputs (metadata order): feature f32 [N*96], src i32 [E], dst i32 [E].
// Output: f32 [N*96].
// ---------------------------------------------------------------------------
extern "C" void kernel_launch(void* const* d_in, const int* in_sizes, int n_in,
                              void* d_out, int out_size) {
    const float* feat = (const float*)d_in[0];
    const int*   src  = (const int*)d_in[1];
    const int*   dst  = (const int*)d_in[2];
    float*       out  = (float*)d_out;

    const int n_nodes = in_sizes[0] / 96;
    const int n_edges = in_sizes[1];
    const int n4      = n_edges / 4;
    const int tail    = n_edges - n4 * 4;

    {
        const int threads = 256;
        if (n4 > 0)
            fill_kernel4<<<(n4 + threads - 1) / threads, threads>>>(
                (const int4*)src, (const int4*)dst, n4, n_nodes);
        if (tail > 0)
            fill_kernel_tail<<<1, 128>>>(src, dst, n4 * 4, n_edges, n_nodes);
    }
    {
        const int threads = 256;                    // 8 warps per block
        const int warps_per_block = threads / 32;
        const int blocks = (n_nodes + warps_per_block - 1) / warps_per_block;
        reduce_kernel<<<blocks, threads>>>(feat, out, n_nodes);
    }
}

// round 8
// speedup vs baseline: 1.3783x; 1.3783x over previous
#include <cuda_runtime.h>

// ---------------------------------------------------------------------------
// Static scratch (no allocations allowed). N_NODES = 50000 in the reference.
// CAP = max binned in-degree: in-degree is Poisson(16); P(deg >= 96) ~ 1e-45.
// Both fill & reduce clamp to CAP (worst case wrong value, never a crash).
//
// g_deg starts zeroed (.bss). fill increments it; reduce consumes the count
// and writes 0 back, restoring the invariant for the next graph replay.
// ---------------------------------------------------------------------------
#define MAXN 50048
#define CAP  96

__device__ int g_deg[MAXN];
__device__ int g_bin[MAXN * CAP];   // ~19.2 MB: src ids grouped by dst

// ---------------------------------------------------------------------------
// Kernel 1: bin edges by destination. 4 edges per thread via int4 loads.
// ---------------------------------------------------------------------------
__global__ void fill_kernel4(const int4* __restrict__ src4,
                             const int4* __restrict__ dst4,
                             int n4, int n_nodes) {
    int i = blockIdx.x * blockDim.x + threadIdx.x;
    if (i >= n4) return;
    int4 s = __ldg(src4 + i);
    int4 t = __ldg(dst4 + i);

    #pragma unroll
    for (int u = 0; u < 4; u++) {
        int ss = (u == 0) ? s.x : (u == 1) ? s.y : (u == 2) ? s.z : s.w;
        int tt = (u == 0) ? t.x : (u == 1) ? t.y : (u == 2) ? t.z : t.w;
        if ((unsigned)ss >= (unsigned)n_nodes || (unsigned)tt >= (unsigned)n_nodes)
            continue;
        int pos = atomicAdd(&g_deg[tt], 1);
        if (pos < CAP) g_bin[tt * CAP + pos] = ss;
    }
}

__global__ void fill_kernel_tail(const int* __restrict__ src,
                                 const int* __restrict__ dst,
                                 int e0, int n_edges, int n_nodes) {
    int e = e0 + blockIdx.x * blockDim.x + threadIdx.x;
    if (e >= n_edges) return;
    int s = __ldg(src + e);
    int t = __ldg(dst + e);
    if ((unsigned)s >= (unsigned)n_nodes || (unsigned)t >= (unsigned)n_nodes) return;
    int pos = atomicAdd(&g_deg[t], 1);
    if (pos < CAP) g_bin[t * CAP + pos] = s;
}

// ---------------------------------------------------------------------------
// Kernel 2: warp-per-node gather-reduce + mean.
// All hot-path loads are UNCONDITIONAL straight-line code so ptxas can
// front-batch consecutive LDG.128s (MLP ~8). R6's predicated loads created a
// BSSY/BSYNC region per load, killing MLP (issue fell to 8.6%).
//   - lanes 24..31 load chunk min(lane,23): valid address, same sectors as
//     lanes 0..1 (no extra traffic), result never stored.
//   - batch slots past k use id=0 (valid row) with a branch-free 0-weight.
// Lane 0 consumes g_deg[node] and resets it for the next graph replay.
// ---------------------------------------------------------------------------
__global__ void __launch_bounds__(256)
reduce_kernel(const float* __restrict__ feat,
              float* __restrict__ out,
              int n_nodes) {
    const int lane = threadIdx.x & 31;
    const int warp = threadIdx.x >> 5;
    const int node = blockIdx.x * (blockDim.x >> 5) + warp;
    if (node >= n_nodes) return;

    int k = 0;
    if (lane == 0) {
        k = g_deg[node];
        g_deg[node] = 0;               // restore invariant for next replay
    }
    k = __shfl_sync(0xffffffffu, k, 0);
    k = k < CAP ? k : CAP;

    const int base  = node * CAP;
    const int chunk = lane < 24 ? lane : 0;     // safe chunk for all 32 lanes
    float4 acc = make_float4(0.f, 0.f, 0.f, 0.f);

    if (k <= 32) {
        // ---- fast path: all ids in one register per lane ----
        int id = 0;                              // default row 0: valid address
        if (lane < k) id = __ldg(g_bin + base + lane);

        int j0 = 0;
        // Full 8-batches: unconditional loads, no weights.
        for (; j0 + 8 <= k; j0 += 8) {
            float4 v[8];
            #pragma unroll
            for (int u = 0; u < 8; u++) {
                int sid = __shfl_sync(0xffffffffu, id, j0 + u);
                v[u] = __ldg(reinterpret_cast<const float4*>(
                                 feat + (size_t)sid * 96) + chunk);
            }
            #pragma unroll
            for (int u = 0; u < 8; u++) {
                acc.x += v[u].x; acc.y += v[u].y;
                acc.z += v[u].z; acc.w += v[u].w;
            }
        }
        // Tail: padded 4-batches, branch-free weight masks out-of-range slots.
        for (; j0 < k; j0 += 4) {
            float4 v[4];
            float  w[4];
            #pragma unroll
            for (int u = 0; u < 4; u++) {
                int sid = __shfl_sync(0xffffffffu, id, (j0 + u) & 31);
                v[u] = __ldg(reinterpret_cast<const float4*>(
                                 feat + (size_t)sid * 96) + chunk);
                w[u] = (j0 + u < k) ? 1.0f : 0.0f;
            }
            #pragma unroll
            for (int u = 0; u < 4; u++) {
                acc.x += v[u].x * w[u]; acc.y += v[u].y * w[u];
                acc.z += v[u].z * w[u]; acc.w += v[u].w * w[u];
            }
        }
    } else {
        // ---- rare generic path (P(k>32) ~ 1e-4): simple loop ----
        int id0 = 0, id1 = 0, id2 = 0;
        if (lane      < k) id0 = __ldg(g_bin + base + lane);
        if (lane + 32 < k) id1 = __ldg(g_bin + base + lane + 32);
        if (lane + 64 < k) id2 = __ldg(g_bin + base + lane + 64);
        for (int j = 0; j < k; j++) {
            int reg = j >> 5;
            int sid = __shfl_sync(0xffffffffu,
                                  reg == 0 ? id0 : (reg == 1 ? id1 : id2),
                                  j & 31);
            float4 v = __ldg(reinterpret_cast<const float4*>(
                                 feat + (size_t)sid * 96) + chunk);
            acc.x += v.x; acc.y += v.y; acc.z += v.z; acc.w += v.w;
        }
    }

    if (lane < 24) {
        const float inv = 1.0f / fmaxf((float)k, 1.0f);
        acc.x *= inv; acc.y *= inv; acc.z *= inv; acc.w *= inv;
        float4* o = reinterpret_cast<float4*>(out + (size_t)node * 96);
        o[lane] = acc;
    }
}

// ---------------------------------------------------------------------------
// Launch. Inputs (metadata order): feature f32 [N*96], src i32 [E], dst i32 [E].
// Output: f32 [N*96].
// ---------------------------------------------------------------------------
extern "C" void kernel_launch(void* const* d_in, const int* in_sizes, int n_in,
                              void* d_out, int out_size) {
    const float* feat = (const float*)d_in[0];
    const int*   src  = (const int*)d_in[1];
    const int*   dst  = (const int*)d_in[2];
    float*       out  = (float*)d_out;

    const int n_nodes = in_sizes[0] / 96;
    const int n_edges = in_sizes[1];
    const int n4      = n_edges / 4;
    const int tail    = n_edges - n4 * 4;

    {
        const int threads = 256;
        if (n4 > 0)
            fill_kernel4<<<(n4 + threads - 1) / threads, threads>>>(
                (const int4*)src, (const int4*)dst, n4, n_nodes);
        if (tail > 0)
            fill_kernel_tail<<<1, 128>>>(src, dst, n4 * 4, n_edges, n_nodes);
    }
    {
        const int threads = 256;                    // 8 warps per block
        const int warps_per_block = threads / 32;
        const int blocks = (n_nodes + warps_per_block - 1) / warps_per_block;
        reduce_kernel<<<blocks, threads>>>(feat, out, n_nodes);
    }
}

// round 9
// speedup vs baseline: 2.6421x; 1.9169x over previous
#include <cuda_runtime.h>

// ---------------------------------------------------------------------------
// Static scratch (no allocations allowed). N_NODES = 50000 in the reference.
// CAP = max binned in-degree: in-degree is Poisson(16); P(deg >= 96) ~ 1e-45.
// Both fill & reduce clamp to CAP (worst case wrong value, never a crash).
//
// g_deg starts zeroed (.bss). fill increments it; reduce consumes the count
// and writes 0 back, restoring the invariant for the next graph replay.
// ---------------------------------------------------------------------------
#define MAXN 50048
#define CAP  96
#define NB   10      // nodes per block in reduce

__device__ int g_deg[MAXN];
__device__ int g_bin[MAXN * CAP];   // ~19.2 MB: src ids grouped by dst

// ---------------------------------------------------------------------------
// Kernel 1: bin edges by destination. 4 edges per thread via int4 loads.
// ---------------------------------------------------------------------------
__global__ void fill_kernel4(const int4* __restrict__ src4,
                             const int4* __restrict__ dst4,
                             int n4, int n_nodes) {
    int i = blockIdx.x * blockDim.x + threadIdx.x;
    if (i >= n4) return;
    int4 s = __ldg(src4 + i);
    int4 t = __ldg(dst4 + i);

    #pragma unroll
    for (int u = 0; u < 4; u++) {
        int ss = (u == 0) ? s.x : (u == 1) ? s.y : (u == 2) ? s.z : s.w;
        int tt = (u == 0) ? t.x : (u == 1) ? t.y : (u == 2) ? t.z : t.w;
        if ((unsigned)ss >= (unsigned)n_nodes || (unsigned)tt >= (unsigned)n_nodes)
            continue;
        int pos = atomicAdd(&g_deg[tt], 1);
        if (pos < CAP) g_bin[tt * CAP + pos] = ss;
    }
}

__global__ void fill_kernel_tail(const int* __restrict__ src,
                                 const int* __restrict__ dst,
                                 int e0, int n_edges, int n_nodes) {
    int e = e0 + blockIdx.x * blockDim.x + threadIdx.x;
    if (e >= n_edges) return;
    int s = __ldg(src + e);
    int t = __ldg(dst + e);
    if ((unsigned)s >= (unsigned)n_nodes || (unsigned)t >= (unsigned)n_nodes) return;
    int pos = atomicAdd(&g_deg[t], 1);
    if (pos < CAP) g_bin[t * CAP + pos] = s;
}

// ---------------------------------------------------------------------------
// Kernel 2: thread-per-(node,chunk) gather-reduce + mean.
// Block handles NB=10 nodes; their src-id lists are staged in shared memory.
// Thread t in [0, NB*24) owns chunk (t%24) of node (t/24) and runs a clean
// independent-iteration loop:
//     acc += feat4[ids[j]*24 + chunk]
// No SHFL, no predication inside the loop -> ptxas can software-pipeline and
// keep multiple LDG.128 in flight (R6/R8 showed shfl-fed manual batching gets
// serialized: regs collapsed to one landing zone, issue fell to <10%).
// Lane 0..NB-1 consume g_deg and reset it for the next graph replay.
// ---------------------------------------------------------------------------
__global__ void __launch_bounds__(256, 4)
reduce_kernel(const float* __restrict__ feat,
              float* __restrict__ out,
              int n_nodes) {
    __shared__ int s_ids[NB * CAP];
    __shared__ int s_k[NB];

    const int t     = threadIdx.x;
    const int node0 = blockIdx.x * NB;

    // Stage degrees (consume + reset).
    if (t < NB) {
        int n = node0 + t;
        int k = 0;
        if (n < n_nodes) {
            k = g_deg[n];
            g_deg[n] = 0;              // restore invariant for next replay
            k = k < CAP ? k : CAP;
        }
        s_k[t] = k;
    }
    __syncthreads();

    // Stage src ids into smem (only the first k per node matter).
    for (int idx = t; idx < NB * CAP; idx += 256) {
        int nl  = idx / CAP;
        int pos = idx - nl * CAP;
        if (pos < s_k[nl])
            s_ids[idx] = __ldg(g_bin + (node0 + nl) * CAP + pos);
    }
    __syncthreads();

    if (t >= NB * 24) return;
    const int nl    = t / 24;
    const int chunk = t - nl * 24;
    const int n     = node0 + nl;
    if (n >= n_nodes) return;

    const int  k   = s_k[nl];
    const int* ids = s_ids + nl * CAP;
    const float4* feat4 = reinterpret_cast<const float4*>(feat);

    float4 acc = make_float4(0.f, 0.f, 0.f, 0.f);
    #pragma unroll 8
    for (int j = 0; j < k; j++) {
        int sid = ids[j];
        float4 v = __ldg(feat4 + (size_t)sid * 24 + chunk);
        acc.x += v.x; acc.y += v.y; acc.z += v.z; acc.w += v.w;
    }

    const float inv = 1.0f / fmaxf((float)k, 1.0f);
    acc.x *= inv; acc.y *= inv; acc.z *= inv; acc.w *= inv;
    reinterpret_cast<float4*>(out)[(size_t)n * 24 + chunk] = acc;
}

// ---------------------------------------------------------------------------
// Launch. Inputs (metadata order): feature f32 [N*96], src i32 [E], dst i32 [E].
// Output: f32 [N*96].
// ---------------------------------------------------------------------------
extern "C" void kernel_launch(void* const* d_in, const int* in_sizes, int n_in,
                              void* d_out, int out_size) {
    const float* feat = (const float*)d_in[0];
    const int*   src  = (const int*)d_in[1];
    const int*   dst  = (const int*)d_in[2];
    float*       out  = (float*)d_out;

    const int n_nodes = in_sizes[0] / 96;
    const int n_edges = in_sizes[1];
    const int n4      = n_edges / 4;
    const int tail    = n_edges - n4 * 4;

    {
        const int threads = 256;
        if (n4 > 0)
            fill_kernel4<<<(n4 + threads - 1) / threads, threads>>>(
                (const int4*)src, (const int4*)dst, n4, n_nodes);
        if (tail > 0)
            fill_kernel_tail<<<1, 128>>>(src, dst, n4 * 4, n_edges, n_nodes);
    }
    {
        const int blocks = (n_nodes + NB - 1) / NB;   // 5000 for N=50000
        reduce_kernel<<<blocks, 256>>>(feat, out, n_nodes);
    }
}

// round 12
// speedup vs baseline: 3.6140x; 1.3679x over previous
#include <cuda_runtime.h>

// ---------------------------------------------------------------------------
// Static scratch (no allocations allowed). N_NODES = 50000 in the reference.
// CAP = max binned in-degree: in-degree is Poisson(16); P(deg >= 96) ~ 1e-45.
// Both fill & reduce clamp to CAP (worst case wrong value, never a crash).
//
// g_deg starts zeroed (.bss). fill increments it; reduce consumes the count
// and writes 0 back, restoring the invariant for the next graph replay.
// g_bin slots >= k are never written (bss zero) -> reading them yields node 0,
// a valid row, which the branch-free weights mask to zero contribution.
// ---------------------------------------------------------------------------
#define MAXN 50048
#define CAP  96
#define NPB  16      // nodes per block (2 per warp, 8 warps)

__device__ int g_deg[MAXN];
__device__ int g_bin[MAXN * CAP];   // ~19.2 MB: src ids grouped by dst

// ---------------------------------------------------------------------------
// Kernel 1: bin edges by destination. 4 edges per thread via int4 loads.
// ---------------------------------------------------------------------------
__global__ void fill_kernel4(const int4* __restrict__ src4,
                             const int4* __restrict__ dst4,
                             int n4, int n_nodes) {
    int i = blockIdx.x * blockDim.x + threadIdx.x;
    if (i >= n4) return;
    int4 s = __ldg(src4 + i);
    int4 t = __ldg(dst4 + i);

    #pragma unroll
    for (int u = 0; u < 4; u++) {
        int ss = (u == 0) ? s.x : (u == 1) ? s.y : (u == 2) ? s.z : s.w;
        int tt = (u == 0) ? t.x : (u == 1) ? t.y : (u == 2) ? t.z : t.w;
        if ((unsigned)ss >= (unsigned)n_nodes || (unsigned)tt >= (unsigned)n_nodes)
            continue;
        int pos = atomicAdd(&g_deg[tt], 1);
        if (pos < CAP) g_bin[tt * CAP + pos] = ss;
    }
}

__global__ void fill_kernel_tail(const int* __restrict__ src,
                                 const int* __restrict__ dst,
                                 int e0, int n_edges, int n_nodes) {
    int e = e0 + blockIdx.x * blockDim.x + threadIdx.x;
    if (e >= n_edges) return;
    int s = __ldg(src + e);
    int t = __ldg(dst + e);
    if ((unsigned)s >= (unsigned)n_nodes || (unsigned)t >= (unsigned)n_nodes) return;
    int pos = atomicAdd(&g_deg[t], 1);
    if (pos < CAP) g_bin[t * CAP + pos] = s;
}

// ---------------------------------------------------------------------------
// Kernel 2: warp-per-2-nodes gather-reduce + mean.
// Evidence so far: latency-bound; maximize occ x MLP with (a) zero branches
// in the hot loop, (b) affine smem-fed addresses (these pipeline; shfl-fed
// ones do not: R8), (c) no occupancy caps (R9's launch_bounds hurt).
// Each warp reduces two nodes simultaneously: 2 independent LDG.128 streams
// per iteration, out-of-range slots masked by branch-free FP weights.
// Lanes 24..31 load chunk 0 (valid dup) and never store.
// ---------------------------------------------------------------------------
__global__ void reduce_kernel(const float* __restrict__ feat,
                              float* __restrict__ out,
                              int n_nodes) {
    __shared__ int s_ids[NPB * CAP];
    __shared__ int s_k[NPB];

    const int t     = threadIdx.x;
    const int node0 = blockIdx.x * NPB;

    // Stage degrees (consume + reset for next graph replay).
    if (t < NPB) {
        int n = node0 + t;
        int k = 0;
        if (n < n_nodes) {
            k = g_deg[n];
            g_deg[n] = 0;
            k = k < CAP ? k : CAP;
        }
        s_k[t] = k;
    }
    __syncthreads();

    // Stage src ids; pad slots >= k with 0 (valid row, weight-masked later).
    for (int idx = t; idx < NPB * CAP; idx += 256) {
        int nl  = idx / CAP;
        int pos = idx - nl * CAP;
        s_ids[idx] = (pos < s_k[nl]) ? __ldg(g_bin + (node0 + nl) * CAP + pos) : 0;
    }
    __syncthreads();

    const int lane  = t & 31;
    const int warp  = t >> 5;
    const int na    = node0 + 2 * warp;      // first node of this warp
    const int nb    = na + 1;                // second node
    const int chunk = lane < 24 ? lane : 0;  // safe duplicate for tail lanes

    const int ka = s_k[2 * warp];
    const int kb = s_k[2 * warp + 1];
    const int kmax = ka > kb ? ka : kb;

    const int* idsa = s_ids + (2 * warp) * CAP;
    const int* idsb = s_ids + (2 * warp + 1) * CAP;
    const float4* feat4 = reinterpret_cast<const float4*>(feat);

    float4 acca = make_float4(0.f, 0.f, 0.f, 0.f);
    float4 accb = make_float4(0.f, 0.f, 0.f, 0.f);

    #pragma unroll 4
    for (int j = 0; j < kmax; j++) {
        int sa = idsa[j];                    // affine LDS (broadcast)
        int sb = idsb[j];
        float4 va = __ldg(feat4 + (size_t)sa * 24 + chunk);
        float4 vb = __ldg(feat4 + (size_t)sb * 24 + chunk);
        float wa = (j < ka) ? 1.0f : 0.0f;   // branch-free masks
        float wb = (j < kb) ? 1.0f : 0.0f;
        acca.x += va.x * wa; acca.y += va.y * wa;
        acca.z += va.z * wa; acca.w += va.w * wa;
        accb.x += vb.x * wb; accb.y += vb.y * wb;
        accb.z += vb.z * wb; accb.w += vb.w * wb;
    }

    if (lane < 24) {
        if (na < n_nodes) {
            const float inv = 1.0f / fmaxf((float)ka, 1.0f);
            float4 r = make_float4(acca.x * inv, acca.y * inv,
                                   acca.z * inv, acca.w * inv);
            reinterpret_cast<float4*>(out)[(size_t)na * 24 + lane] = r;
        }
        if (nb < n_nodes) {
            const float inv = 1.0f / fmaxf((float)kb, 1.0f);
            float4 r = make_float4(accb.x * inv, accb.y * inv,
                                   accb.z * inv, accb.w * inv);
            reinterpret_cast<float4*>(out)[(size_t)nb * 24 + lane] = r;
        }
    }
}

// ---------------------------------------------------------------------------
// Launch. Inputs (metadata order): feature f32 [N*96], src i32 [E], dst i32 [E].
// Output: f32 [N*96].
// ---------------------------------------------------------------------------
extern "C" void kernel_launch(void* const* d_in, const int* in_sizes, int n_in,
                              void* d_out, int out_size) {
    const float* feat = (const float*)d_in[0];
    const int*   src  = (const int*)d_in[1];
    const int*   dst  = (const int*)d_in[2];
    float*       out  = (float*)d_out;

    const int n_nodes = in_sizes[0] / 96;
    const int n_edges = in_sizes[1];
    const int n4      = n_edges / 4;
    const int tail    = n_edges - n4 * 4;

    {
        const int threads = 256;
        if (n4 > 0)
            fill_kernel4<<<(n4 + threads - 1) / threads, threads>>>(
                (const int4*)src, (const int4*)dst, n4, n_nodes);
        if (tail > 0)
            fill_kernel_tail<<<1, 128>>>(src, dst, n4 * 4, n_edges, n_nodes);
    }
    {
        const int blocks = (n_nodes + NPB - 1) / NPB;   // 3125 for N=50000
        reduce_kernel<<<blocks, 256>>>(feat, out, n_nodes);
    }
}